// round 2
// baseline (speedup 1.0000x reference)
#include <cuda_runtime.h>
#include <math.h>

#define cB 32
#define cS 64
#define cT 64
#define cE 512
#define cH 1024
#define cG 4096
#define cV 32000

// ---- scratch layout (float offsets) ----
#define OFF_GF      0ull
#define OFF_GB      8388608ull
#define OFF_GD      16777216ull
#define OFF_GATES   25165824ull   // 4 slots x 131072
#define OFF_HF      25690112ull
#define OFF_CF      25722880ull
#define OFF_HB      25755648ull
#define OFF_CB      25788416ull
#define OFF_SUMF    25821184ull
#define OFF_SUMB    25853952ull
#define OFF_HD      25886720ull
#define OFF_CD      25919488ull
#define OFF_DECB    25952256ull
#define OFF_HDEC    25985024ull   // T*B*H
#define OFF_OUTS    28082176ull
#define SCR_TOTAL   30179328ull

__device__ float g_scr[SCR_TOTAL];

__device__ __forceinline__ float sigf(float x) { return 1.0f / (1.0f + expf(-x)); }

// ============ gather-GEMM: O[m,n] = emb[tok]@W.T + bi + bh  (M=2048,N=4096,K=512)
__global__ __launch_bounds__(256, 2) void k_prep(
    const int* __restrict__ tok, const float* __restrict__ emb,
    const float* __restrict__ W, const float* __restrict__ bi,
    const float* __restrict__ bh, float* __restrict__ O)
{
    __shared__ float As[16][128];
    __shared__ float Bs[16][128];
    const int m0 = blockIdx.x * 128, n0 = blockIdx.y * 128;
    const int tid = threadIdx.x, tx = tid & 15, ty = tid >> 4;
    float acc[8][8];
    #pragma unroll
    for (int i = 0; i < 8; i++)
        #pragma unroll
        for (int j = 0; j < 8; j++) acc[i][j] = 0.f;

    for (int k0 = 0; k0 < cE; k0 += 16) {
        #pragma unroll
        for (int L = 0; L < 2; L++) {
            int flat = tid + (L << 8);
            int r = flat >> 2, c4 = (flat & 3) << 2;
            int m = m0 + r;
            int trow = tok[(m & 31) * 64 + (m >> 5)];
            float4 v = *(const float4*)&emb[(size_t)trow * cE + k0 + c4];
            As[c4+0][r]=v.x; As[c4+1][r]=v.y; As[c4+2][r]=v.z; As[c4+3][r]=v.w;
        }
        #pragma unroll
        for (int L = 0; L < 2; L++) {
            int flat = tid + (L << 8);
            int r = flat >> 2, c4 = (flat & 3) << 2;
            float4 v = *(const float4*)&W[(size_t)(n0 + r) * cE + k0 + c4];
            Bs[c4+0][r]=v.x; Bs[c4+1][r]=v.y; Bs[c4+2][r]=v.z; Bs[c4+3][r]=v.w;
        }
        __syncthreads();
        #pragma unroll
        for (int kk = 0; kk < 16; kk++) {
            float4 a0 = *(const float4*)&As[kk][ty*8];
            float4 a1 = *(const float4*)&As[kk][ty*8+4];
            float4 b0 = *(const float4*)&Bs[kk][tx*8];
            float4 b1 = *(const float4*)&Bs[kk][tx*8+4];
            float av[8] = {a0.x,a0.y,a0.z,a0.w,a1.x,a1.y,a1.z,a1.w};
            float bv[8] = {b0.x,b0.y,b0.z,b0.w,b1.x,b1.y,b1.z,b1.w};
            #pragma unroll
            for (int i = 0; i < 8; i++)
                #pragma unroll
                for (int j = 0; j < 8; j++) acc[i][j] += av[i]*bv[j];
        }
        __syncthreads();
    }
    #pragma unroll
    for (int i = 0; i < 8; i++) {
        int m = m0 + ty*8 + i;
        #pragma unroll
        for (int j = 0; j < 8; j++) {
            int n = n0 + tx*8 + j;
            O[(size_t)m*cG + n] = acc[i][j] + bi[n] + bh[n];
        }
    }
}

// ============ recurrent GEMM: out[b,n] = sum_k h[b,k]*W[n,k], M=32, BN=128, splitK
__global__ __launch_bounds__(256) void k_step(
    const float* __restrict__ hA0, const float* __restrict__ W0, float* __restrict__ out0,
    const float* __restrict__ hA1, const float* __restrict__ W1, float* __restrict__ out1)
{
    const float* hA = blockIdx.y ? hA1 : hA0;
    const float* W  = blockIdx.y ? W1 : W0;
    float* out = (blockIdx.y ? out1 : out0) + (size_t)blockIdx.z * 131072;
    __shared__ float As[16][33];
    __shared__ float Bs[16][128];
    const int tid = threadIdx.x, n0 = blockIdx.x * 128;
    const int kn = cH / gridDim.z, kbeg = blockIdx.z * kn;
    const int tx = tid & 31, ty = tid >> 5;
    float acc[4][4];
    #pragma unroll
    for (int i = 0; i < 4; i++)
        #pragma unroll
        for (int j = 0; j < 4; j++) acc[i][j] = 0.f;

    for (int k0 = kbeg; k0 < kbeg + kn; k0 += 16) {
        if (tid < 128) {
            int r = tid >> 2, c4 = (tid & 3) << 2;
            float4 v = *(const float4*)&hA[r * cH + k0 + c4];
            As[c4+0][r]=v.x; As[c4+1][r]=v.y; As[c4+2][r]=v.z; As[c4+3][r]=v.w;
        }
        #pragma unroll
        for (int L = 0; L < 2; L++) {
            int flat = tid + (L << 8);
            int r = flat >> 2, c4 = (flat & 3) << 2;
            float4 v = *(const float4*)&W[(size_t)(n0 + r) * cH + k0 + c4];
            Bs[c4+0][r]=v.x; Bs[c4+1][r]=v.y; Bs[c4+2][r]=v.z; Bs[c4+3][r]=v.w;
        }
        __syncthreads();
        #pragma unroll
        for (int kk = 0; kk < 16; kk++) {
            float a0=As[kk][ty*4+0], a1=As[kk][ty*4+1], a2=As[kk][ty*4+2], a3=As[kk][ty*4+3];
            float4 b = *(const float4*)&Bs[kk][tx*4];
            acc[0][0]+=a0*b.x; acc[0][1]+=a0*b.y; acc[0][2]+=a0*b.z; acc[0][3]+=a0*b.w;
            acc[1][0]+=a1*b.x; acc[1][1]+=a1*b.y; acc[1][2]+=a1*b.z; acc[1][3]+=a1*b.w;
            acc[2][0]+=a2*b.x; acc[2][1]+=a2*b.y; acc[2][2]+=a2*b.z; acc[2][3]+=a2*b.w;
            acc[3][0]+=a3*b.x; acc[3][1]+=a3*b.y; acc[3][2]+=a3*b.z; acc[3][3]+=a3*b.w;
        }
        __syncthreads();
    }
    #pragma unroll
    for (int i = 0; i < 4; i++) {
        int b = ty*4 + i;
        #pragma unroll
        for (int j = 0; j < 4; j++)
            out[b*cG + n0 + tx*4 + j] = acc[i][j];
    }
}

// ============ encoder elementwise LSTM (both directions)
__global__ void k_elem_enc(const float* __restrict__ gates,
                           const float* __restrict__ Gf_t, const float* __restrict__ Gb_t,
                           float* __restrict__ hf, float* __restrict__ cf,
                           float* __restrict__ hb, float* __restrict__ cb,
                           float* __restrict__ sumf, float* __restrict__ sumb)
{
    int idx = blockIdx.x * 256 + threadIdx.x;
    int dir = idx >> 15;
    int u = idx & 32767;
    int b = u >> 10, j = u & 1023;
    int base = b * cG;
    const float* Gx = (dir ? Gb_t : Gf_t) + base;
    const float* p0 = gates + dir * 262144 + base;
    const float* p1 = p0 + 131072;
    float gi = Gx[j]      + p0[j]      + p1[j];
    float gf = Gx[1024+j] + p0[1024+j] + p1[1024+j];
    float gg = Gx[2048+j] + p0[2048+j] + p1[2048+j];
    float go = Gx[3072+j] + p0[3072+j] + p1[3072+j];
    float* cp = dir ? cb : cf;
    float* hp = dir ? hb : hf;
    float* sp = dir ? sumb : sumf;
    float c = sigf(gf) * cp[u] + sigf(gi) * tanhf(gg);
    cp[u] = c;
    float h = sigf(go) * tanhf(c);
    hp[u] = h;
    sp[u] += h;
}

// ============ decoder elementwise LSTM (4 split-K partials)
__global__ void k_elem_dec(const float* __restrict__ gates, const float* __restrict__ Gd_t,
                           float* __restrict__ hd, float* __restrict__ cd,
                           float* __restrict__ hdec_t)
{
    int u = blockIdx.x * 256 + threadIdx.x;
    int b = u >> 10, j = u & 1023;
    int base = b * cG;
    float gi = Gd_t[base+j], gf = Gd_t[base+1024+j];
    float gg = Gd_t[base+2048+j], go = Gd_t[base+3072+j];
    #pragma unroll
    for (int z = 0; z < 4; z++) {
        const float* p = gates + z * 131072 + base;
        gi += p[j]; gf += p[1024+j]; gg += p[2048+j]; go += p[3072+j];
    }
    float c = sigf(gf) * cd[u] + sigf(gi) * tanhf(gg);
    cd[u] = c;
    float h = sigf(go) * tanhf(c);
    hd[u] = h;
    hdec_t[u] = h;
}

__global__ void k_zero(float* __restrict__ p, int n)
{
    int i = blockIdx.x * 256 + threadIdx.x;
    if (i < n) p[i] = 0.f;
}

__global__ void k_initdec(const float* __restrict__ hf, const float* __restrict__ hb,
                          const float* __restrict__ cf, const float* __restrict__ cb,
                          float* __restrict__ hd, float* __restrict__ cd)
{
    int u = blockIdx.x * 256 + threadIdx.x;
    hd[u] = hf[u] + hb[u];
    cd[u] = cf[u] + cb[u];
}

// ============ decoder constant bias partials: parts[z][b,n] = sum_kslice applied[b,k]*Wc[n][1024+k]
__global__ __launch_bounds__(256) void k_decbias(
    const float* __restrict__ sumf, const float* __restrict__ sumb,
    const float* __restrict__ Wc, float* __restrict__ parts)
{
    __shared__ float As[16][33];
    __shared__ float Bs[16][128];
    const int tid = threadIdx.x, n0 = blockIdx.x * 128;
    const int kn = 2048 / gridDim.z, kbeg = blockIdx.z * kn;
    const int tx = tid & 31, ty = tid >> 5;
    float acc[4][4];
    #pragma unroll
    for (int i = 0; i < 4; i++)
        #pragma unroll
        for (int j = 0; j < 4; j++) acc[i][j] = 0.f;

    for (int k0 = kbeg; k0 < kbeg + kn; k0 += 16) {
        if (tid < 128) {
            int r = tid >> 2, c4 = (tid & 3) << 2;
            int k = k0 + c4;
            const float* src = (k < 1024) ? &sumf[r*cH + k] : &sumb[r*cH + k - 1024];
            float4 v = *(const float4*)src;
            As[c4+0][r]=v.x; As[c4+1][r]=v.y; As[c4+2][r]=v.z; As[c4+3][r]=v.w;
        }
        #pragma unroll
        for (int L = 0; L < 2; L++) {
            int flat = tid + (L << 8);
            int r = flat >> 2, c4 = (flat & 3) << 2;
            float4 v = *(const float4*)&Wc[(size_t)(n0 + r) * 3072 + 1024 + k0 + c4];
            Bs[c4+0][r]=v.x; Bs[c4+1][r]=v.y; Bs[c4+2][r]=v.z; Bs[c4+3][r]=v.w;
        }
        __syncthreads();
        #pragma unroll
        for (int kk = 0; kk < 16; kk++) {
            float a0=As[kk][ty*4+0], a1=As[kk][ty*4+1], a2=As[kk][ty*4+2], a3=As[kk][ty*4+3];
            float4 b = *(const float4*)&Bs[kk][tx*4];
            acc[0][0]+=a0*b.x; acc[0][1]+=a0*b.y; acc[0][2]+=a0*b.z; acc[0][3]+=a0*b.w;
            acc[1][0]+=a1*b.x; acc[1][1]+=a1*b.y; acc[1][2]+=a1*b.z; acc[1][3]+=a1*b.w;
            acc[2][0]+=a2*b.x; acc[2][1]+=a2*b.y; acc[2][2]+=a2*b.z; acc[2][3]+=a2*b.w;
            acc[3][0]+=a3*b.x; acc[3][1]+=a3*b.y; acc[3][2]+=a3*b.z; acc[3][3]+=a3*b.w;
        }
        __syncthreads();
    }
    float* out = parts + (size_t)blockIdx.z * 32768;
    #pragma unroll
    for (int i = 0; i < 4; i++) {
        int b = ty*4 + i;
        #pragma unroll
        for (int j = 0; j < 4; j++)
            out[b*cH + n0 + tx*4 + j] = acc[i][j];
    }
}

__global__ void k_redbias(const float* __restrict__ parts, const float* __restrict__ bc,
                          float* __restrict__ decb)
{
    int u = blockIdx.x * 256 + threadIdx.x;   // 0..32767
    float a = bc[u & 1023];
    #pragma unroll
    for (int z = 0; z < 8; z++) a += parts[z * 32768 + u];
    decb[u] = a;
}

// ============ outs = tanh(Hdec @ Wc[:, :1024].T + decb[b])   M=2048,N=1024,K=1024
__global__ __launch_bounds__(256, 2) void k_outs(
    const float* __restrict__ A, const float* __restrict__ Wc,
    const float* __restrict__ decb, float* __restrict__ O)
{
    __shared__ float As[16][128];
    __shared__ float Bs[16][128];
    const int m0 = blockIdx.x * 128, n0 = blockIdx.y * 128;
    const int tid = threadIdx.x, tx = tid & 15, ty = tid >> 4;
    float acc[8][8];
    #pragma unroll
    for (int i = 0; i < 8; i++)
        #pragma unroll
        for (int j = 0; j < 8; j++) acc[i][j] = 0.f;

    for (int k0 = 0; k0 < cH; k0 += 16) {
        #pragma unroll
        for (int L = 0; L < 2; L++) {
            int flat = tid + (L << 8);
            int r = flat >> 2, c4 = (flat & 3) << 2;
            float4 v = *(const float4*)&A[(size_t)(m0 + r) * cH + k0 + c4];
            As[c4+0][r]=v.x; As[c4+1][r]=v.y; As[c4+2][r]=v.z; As[c4+3][r]=v.w;
        }
        #pragma unroll
        for (int L = 0; L < 2; L++) {
            int flat = tid + (L << 8);
            int r = flat >> 2, c4 = (flat & 3) << 2;
            float4 v = *(const float4*)&Wc[(size_t)(n0 + r) * 3072 + k0 + c4];
            Bs[c4+0][r]=v.x; Bs[c4+1][r]=v.y; Bs[c4+2][r]=v.z; Bs[c4+3][r]=v.w;
        }
        __syncthreads();
        #pragma unroll
        for (int kk = 0; kk < 16; kk++) {
            float4 a0 = *(const float4*)&As[kk][ty*8];
            float4 a1 = *(const float4*)&As[kk][ty*8+4];
            float4 b0 = *(const float4*)&Bs[kk][tx*8];
            float4 b1 = *(const float4*)&Bs[kk][tx*8+4];
            float av[8] = {a0.x,a0.y,a0.z,a0.w,a1.x,a1.y,a1.z,a1.w};
            float bv[8] = {b0.x,b0.y,b0.z,b0.w,b1.x,b1.y,b1.z,b1.w};
            #pragma unroll
            for (int i = 0; i < 8; i++)
                #pragma unroll
                for (int j = 0; j < 8; j++) acc[i][j] += av[i]*bv[j];
        }
        __syncthreads();
    }
    #pragma unroll
    for (int i = 0; i < 8; i++) {
        int m = m0 + ty*8 + i;
        #pragma unroll
        for (int j = 0; j < 8; j++) {
            int n = n0 + tx*8 + j;
            O[(size_t)m*cH + n] = tanhf(acc[i][j] + decb[(m & 31) * cH + n]);
        }
    }
}

// ============ logits = outs @ Wout.T + bout, scattered to output layout (B,T,V)
__global__ __launch_bounds__(256, 2) void k_logits(
    const float* __restrict__ A, const float* __restrict__ W,
    const float* __restrict__ bout, float* __restrict__ out)
{
    __shared__ float As[16][128];
    __shared__ float Bs[16][128];
    const int m0 = blockIdx.x * 128, n0 = blockIdx.y * 128;
    const int tid = threadIdx.x, tx = tid & 15, ty = tid >> 4;
    float acc[8][8];
    #pragma unroll
    for (int i = 0; i < 8; i++)
        #pragma unroll
        for (int j = 0; j < 8; j++) acc[i][j] = 0.f;

    for (int k0 = 0; k0 < cH; k0 += 16) {
        #pragma unroll
        for (int L = 0; L < 2; L++) {
            int flat = tid + (L << 8);
            int r = flat >> 2, c4 = (flat & 3) << 2;
            float4 v = *(const float4*)&A[(size_t)(m0 + r) * cH + k0 + c4];
            As[c4+0][r]=v.x; As[c4+1][r]=v.y; As[c4+2][r]=v.z; As[c4+3][r]=v.w;
        }
        #pragma unroll
        for (int L = 0; L < 2; L++) {
            int flat = tid + (L << 8);
            int r = flat >> 2, c4 = (flat & 3) << 2;
            float4 v = *(const float4*)&W[(size_t)(n0 + r) * cH + k0 + c4];
            Bs[c4+0][r]=v.x; Bs[c4+1][r]=v.y; Bs[c4+2][r]=v.z; Bs[c4+3][r]=v.w;
        }
        __syncthreads();
        #pragma unroll
        for (int kk = 0; kk < 16; kk++) {
            float4 a0 = *(const float4*)&As[kk][ty*8];
            float4 a1 = *(const float4*)&As[kk][ty*8+4];
            float4 b0 = *(const float4*)&Bs[kk][tx*8];
            float4 b1 = *(const float4*)&Bs[kk][tx*8+4];
            float av[8] = {a0.x,a0.y,a0.z,a0.w,a1.x,a1.y,a1.z,a1.w};
            float bv[8] = {b0.x,b0.y,b0.z,b0.w,b1.x,b1.y,b1.z,b1.w};
            #pragma unroll
            for (int i = 0; i < 8; i++)
                #pragma unroll
                for (int j = 0; j < 8; j++) acc[i][j] += av[i]*bv[j];
        }
        __syncthreads();
    }
    #pragma unroll
    for (int i = 0; i < 8; i++) {
        int m = m0 + ty*8 + i;
        size_t rowbase = (size_t)((m & 31) * 64 + (m >> 5)) * cV;   // (b,t) row
        #pragma unroll
        for (int j = 0; j < 8; j++) {
            int n = n0 + tx*8 + j;
            out[rowbase + n] = acc[i][j] + bout[n];
        }
    }
}

// ============ in-place log_softmax over V + argmax
__global__ void k_softmax(float* __restrict__ out, float* __restrict__ preds, int write_preds)
{
    int r = blockIdx.x;
    float* row = out + (size_t)r * cV;
    int tid = threadIdx.x;
    __shared__ float sm[256];
    __shared__ int   si[256];
    float m = -1e30f; int mi = 0;
    for (int v = tid; v < cV; v += 256) {
        float x = row[v];
        if (x > m) { m = x; mi = v; }
    }
    sm[tid] = m; si[tid] = mi;
    __syncthreads();
    for (int s = 128; s > 0; s >>= 1) {
        if (tid < s) {
            float o = sm[tid+s]; int oi = si[tid+s];
            if (o > sm[tid] || (o == sm[tid] && oi < si[tid])) { sm[tid] = o; si[tid] = oi; }
        }
        __syncthreads();
    }
    float rowmax = sm[0];
    int rowarg = si[0];
    float acc = 0.f;
    for (int v = tid; v < cV; v += 256) acc += expf(row[v] - rowmax);
    sm[tid] = acc;
    __syncthreads();
    for (int s = 128; s > 0; s >>= 1) {
        if (tid < s) sm[tid] += sm[tid+s];
        __syncthreads();
    }
    float lse = rowmax + logf(sm[0]);
    for (int v = tid; v < cV; v += 256) row[v] -= lse;
    if (tid == 0 && write_preds) preds[r] = (float)rowarg;
}

extern "C" void kernel_launch(void* const* d_in, const int* in_sizes, int n_in,
                              void* d_out, int out_size)
{
    const int*   inputs  = (const int*)d_in[0];
    const int*   targets = (const int*)d_in[1];
    const float* emb_src = (const float*)d_in[2];
    const float* Wih_f = (const float*)d_in[3];
    const float* Whh_f = (const float*)d_in[4];
    const float* bih_f = (const float*)d_in[5];
    const float* bhh_f = (const float*)d_in[6];
    const float* Wih_b = (const float*)d_in[7];
    const float* Whh_b = (const float*)d_in[8];
    const float* bih_b = (const float*)d_in[9];
    const float* bhh_b = (const float*)d_in[10];
    const float* emb_tgt = (const float*)d_in[11];
    const float* Wih_d = (const float*)d_in[12];
    const float* Whh_d = (const float*)d_in[13];
    const float* bih_d = (const float*)d_in[14];
    const float* bhh_d = (const float*)d_in[15];
    /* d_in[16] = Wattn: provably unused (softmax over singleton axis) */
    const float* Wc   = (const float*)d_in[17];
    const float* bc   = (const float*)d_in[18];
    const float* Wout = (const float*)d_in[19];
    const float* bout = (const float*)d_in[20];
    float* out = (float*)d_out;

    float* scr = nullptr;
    cudaGetSymbolAddress((void**)&scr, g_scr);
    float* GF    = scr + OFF_GF;
    float* GB    = scr + OFF_GB;
    float* GD    = scr + OFF_GD;
    float* GATES = scr + OFF_GATES;
    float* HF = scr + OFF_HF;  float* CF = scr + OFF_CF;
    float* HB = scr + OFF_HB;  float* CB = scr + OFF_CB;
    float* SF = scr + OFF_SUMF; float* SB = scr + OFF_SUMB;
    float* HD = scr + OFF_HD;  float* CD = scr + OFF_CD;
    float* DECB = scr + OFF_DECB;
    float* HDEC = scr + OFF_HDEC;
    float* OUTS = scr + OFF_OUTS;

    // batched gate pre-activations
    k_prep<<<dim3(16, 32), 256>>>(inputs,  emb_src, Wih_f, bih_f, bhh_f, GF);
    k_prep<<<dim3(16, 32), 256>>>(inputs,  emb_src, Wih_b, bih_b, bhh_b, GB);
    k_prep<<<dim3(16, 32), 256>>>(targets, emb_tgt, Wih_d, bih_d, bhh_d, GD);
    // zero h/c/sums (contiguous region)
    k_zero<<<768, 256>>>(HF, 196608);

    // encoder: both directions per iteration
    for (int t = 0; t < cS; t++) {
        k_step<<<dim3(32, 2, 2), 256>>>(HF, Whh_f, GATES, HB, Whh_b, GATES + 262144);
        k_elem_enc<<<256, 256>>>(GATES, GF + (size_t)t * 131072,
                                 GB + (size_t)(cS - 1 - t) * 131072,
                                 HF, CF, HB, CB, SF, SB);
    }

    k_initdec<<<128, 256>>>(HF, HB, CF, CB, HD, CD);
    k_decbias<<<dim3(8, 1, 8), 256>>>(SF, SB, Wc, GATES);
    k_redbias<<<128, 256>>>(GATES, bc, DECB);

    // decoder
    for (int t = 0; t < cT; t++) {
        k_step<<<dim3(32, 1, 4), 256>>>(HD, Whh_d, GATES, HD, Whh_d, GATES);
        k_elem_dec<<<128, 256>>>(GATES, GD + (size_t)t * 131072, HD, CD,
                                 HDEC + (size_t)t * 32768);
    }

    k_outs<<<dim3(16, 8), 256>>>(HDEC, Wc, DECB, OUTS);
    k_logits<<<dim3(16, 250), 256>>>(OUTS, Wout, bout, out);

    int write_preds = (out_size >= cB * cT * cV + cB * cT) ? 1 : 0;
    k_softmax<<<2048, 256>>>(out, out + (size_t)cB * cT * cV, write_preds);
}